// round 1
// baseline (speedup 1.0000x reference)
#include <cuda_runtime.h>
#include <cstdint>

// Problem constants
#define BSZ   2048
#define D     2048
#define MM    6
#define THRESH 30
#define LAM   1.0e-4f
#define LDF   (MM*D)          // 12288, row stride of X / F storage [bsz, m, d]
#define NITER (THRESH-1)      // 29

// ---------------- device scratch (no allocations allowed) ----------------
__device__ float  g_F[(size_t)BSZ * MM * D];   // F history, [bsz, m, d]
__device__ float  g_alpha[BSZ * 8];
__device__ float  g_GGt[BSZ * 36];
__device__ double g_norms[2 * NITER + 2];

// ---------------- small utility kernels ----------------
__global__ void zero_norms_kernel(double* norms) {
    int i = threadIdx.x;
    if (i < 2 * NITER + 2) norms[i] = 0.0;
}

// X[:,0,:] = x0
__global__ void scatter_x0_kernel(const float* __restrict__ x0, float* __restrict__ X) {
    int idx = blockIdx.x * blockDim.x + threadIdx.x;
    if (idx >= BSZ * D) return;
    int b = idx >> 11;          // /2048
    int c = idx & (D - 1);
    X[(size_t)b * LDF + c] = x0[idx];
}

// result = X[:, up, :]
__global__ void gather_result_kernel(const float* __restrict__ X, float* __restrict__ res, int up) {
    int idx = blockIdx.x * blockDim.x + threadIdx.x;
    if (idx >= BSZ * D) return;
    int b = idx >> 11;
    int c = idx & (D - 1);
    res[idx] = X[(size_t)b * LDF + up * D + c];
}

// ---------------- SGEMM: C = tanh(A @ W + bias) ----------------
// A: M x K row-major with row stride lda, W: K x N row-major (ld = D),
// C: M x N with row stride ldc. M = N = K = 2048. Tiles 128x128x16, 256 thr, 8x8/thr.
__global__ __launch_bounds__(256, 2)
void gemm_bias_tanh_kernel(const float* __restrict__ A, int lda,
                           const float* __restrict__ W,
                           const float* __restrict__ bias,
                           float* __restrict__ C, int ldc)
{
    __shared__ float As[16][128];   // transposed A tile: As[k][m]
    __shared__ float Bs[16][128];   // Bs[k][n]

    const int tid = threadIdx.x;
    const int bm = blockIdx.y * 128;
    const int bn = blockIdx.x * 128;
    const int rowb = (tid >> 4) << 3;   // 0..120
    const int colb = (tid & 15) << 3;   // 0..120

    float acc[8][8];
#pragma unroll
    for (int i = 0; i < 8; i++)
#pragma unroll
        for (int j = 0; j < 8; j++) acc[i][j] = 0.f;

    for (int kt = 0; kt < D; kt += 16) {
        // load A tile: 128 rows x 16 cols = 512 float4, 2 per thread
#pragma unroll
        for (int l = 0; l < 2; l++) {
            int idx = tid + l * 256;
            int r = idx >> 2;
            int c4 = idx & 3;
            float4 v = *(const float4*)(A + (size_t)(bm + r) * lda + kt + c4 * 4);
            As[c4 * 4 + 0][r] = v.x;
            As[c4 * 4 + 1][r] = v.y;
            As[c4 * 4 + 2][r] = v.z;
            As[c4 * 4 + 3][r] = v.w;
        }
        // load W tile: 16 rows x 128 cols = 512 float4, 2 per thread
#pragma unroll
        for (int l = 0; l < 2; l++) {
            int idx = tid + l * 256;
            int r = idx >> 5;
            int c4 = idx & 31;
            *(float4*)(&Bs[r][c4 * 4]) =
                *(const float4*)(W + (size_t)(kt + r) * D + bn + c4 * 4);
        }
        __syncthreads();

#pragma unroll
        for (int kk = 0; kk < 16; kk++) {
            float a[8], bb[8];
            *(float4*)(a)     = *(const float4*)(&As[kk][rowb]);
            *(float4*)(a + 4) = *(const float4*)(&As[kk][rowb + 4]);
            *(float4*)(bb)     = *(const float4*)(&Bs[kk][colb]);
            *(float4*)(bb + 4) = *(const float4*)(&Bs[kk][colb + 4]);
#pragma unroll
            for (int i = 0; i < 8; i++)
#pragma unroll
                for (int j = 0; j < 8; j++)
                    acc[i][j] += a[i] * bb[j];
        }
        __syncthreads();
    }

#pragma unroll
    for (int i = 0; i < 8; i++) {
        size_t gr = (size_t)(bm + rowb + i);
#pragma unroll
        for (int j = 0; j < 8; j++) {
            int gc = bn + colb + j;
            C[gr * ldc + gc] = tanhf(acc[i][j] + bias[gc]);
        }
    }
}

// ---------------- batched Gram: GGt[b,i,j] = sum_d (F-X)[b,i,d]*(F-X)[b,j,d] ----------------
__global__ __launch_bounds__(256)
void gram_kernel(const float* __restrict__ F, const float* __restrict__ X,
                 float* __restrict__ GGt, int n)
{
    int b = blockIdx.x;
    const float* Fb = F + (size_t)b * LDF;
    const float* Xb = X + (size_t)b * LDF;

    float acc[21];
#pragma unroll
    for (int p = 0; p < 21; p++) acc[p] = 0.f;

    for (int dd = threadIdx.x; dd < D; dd += 256) {
        float g[6];
#pragma unroll
        for (int i = 0; i < 6; i++)
            g[i] = (i < n) ? (Fb[i * D + dd] - Xb[i * D + dd]) : 0.f;
        int p = 0;
#pragma unroll
        for (int i = 0; i < 6; i++)
#pragma unroll
            for (int j = i; j < 6; j++) {
                acc[p] += g[i] * g[j];
                p++;
            }
    }

    __shared__ float sm[256][21];
#pragma unroll
    for (int p = 0; p < 21; p++) sm[threadIdx.x][p] = acc[p];
    __syncthreads();
    for (int s = 128; s > 0; s >>= 1) {
        if (threadIdx.x < s) {
#pragma unroll
            for (int p = 0; p < 21; p++) sm[threadIdx.x][p] += sm[threadIdx.x + s][p];
        }
        __syncthreads();
    }
    if (threadIdx.x == 0) {
        float* out = GGt + (size_t)b * 36;
        int p = 0;
        for (int i = 0; i < 6; i++)
            for (int j = i; j < 6; j++) {
                float v = sm[0][p++];
                if (i == j) v += LAM;
                out[i * 6 + j] = v;
                out[j * 6 + i] = v;
            }
    }
}

// ---------------- per-batch (n+1)x(n+1) bordered solve ----------------
__global__ void solve_kernel(const float* __restrict__ GGt, float* __restrict__ alpha, int n)
{
    int b = blockIdx.x * blockDim.x + threadIdx.x;
    if (b >= BSZ) return;
    const int s = n + 1;
    float H[7][7];
    float y[7];
    H[0][0] = 0.f; y[0] = 1.f;
    for (int i = 1; i < s; i++) { H[0][i] = 1.f; H[i][0] = 1.f; y[i] = 0.f; }
    const float* G = GGt + (size_t)b * 36;
    for (int i = 0; i < n; i++)
        for (int j = 0; j < n; j++)
            H[i + 1][j + 1] = G[i * 6 + j];

    // Gaussian elimination with partial pivoting
    for (int c = 0; c < s; c++) {
        int piv = c;
        float mx = fabsf(H[c][c]);
        for (int r = c + 1; r < s; r++) {
            float v = fabsf(H[r][c]);
            if (v > mx) { mx = v; piv = r; }
        }
        if (piv != c) {
            for (int cc = 0; cc < s; cc++) {
                float t = H[c][cc]; H[c][cc] = H[piv][cc]; H[piv][cc] = t;
            }
            float t = y[c]; y[c] = y[piv]; y[piv] = t;
        }
        float inv = 1.f / H[c][c];
        for (int r = c + 1; r < s; r++) {
            float f = H[r][c] * inv;
            if (f != 0.f) {
                for (int cc = c; cc < s; cc++) H[r][cc] -= f * H[c][cc];
                y[r] -= f * y[c];
            }
        }
    }
    float sol[7];
    for (int r = s - 1; r >= 0; r--) {
        float a = y[r];
        for (int cc = r + 1; cc < s; cc++) a -= H[r][cc] * sol[cc];
        sol[r] = a / H[r][r];
    }
    float* ab = alpha + b * 8;
    for (int i = 0; i < 6; i++) ab[i] = (i < n) ? sol[i + 1] : 0.f;
}

// ---------------- xnew = sum_i alpha[b,i] * F[b,i,:]  (beta = 1) ----------------
__global__ __launch_bounds__(256)
void combine_kernel(const float* __restrict__ F, const float* __restrict__ alpha,
                    float* __restrict__ X, int n, int up)
{
    int b = blockIdx.y;
    int col = blockIdx.x * 256 + threadIdx.x;
    const float* Fb = F + (size_t)b * LDF;
    const float* ab = alpha + b * 8;
    float acc = 0.f;
#pragma unroll
    for (int i = 0; i < 6; i++)
        if (i < n) acc += ab[i] * Fb[i * D + col];
    X[(size_t)b * LDF + up * D + col] = acc;
}

// ---------------- norms: sum (fnew-xnew)^2 and sum fnew^2 ----------------
__global__ __launch_bounds__(256)
void norm_kernel(const float* __restrict__ F, const float* __restrict__ X,
                 int up, double* __restrict__ out)
{
    double sg = 0.0, sf = 0.0;
    int total = BSZ * D;
    for (int idx = blockIdx.x * blockDim.x + threadIdx.x; idx < total;
         idx += gridDim.x * blockDim.x) {
        int b = idx >> 11;
        int c = idx & (D - 1);
        size_t off = (size_t)b * LDF + up * D + c;
        float f = F[off];
        float x = X[off];
        float g = f - x;
        sg += (double)g * (double)g;
        sf += (double)f * (double)f;
    }
    __shared__ double smg[256];
    __shared__ double smf[256];
    smg[threadIdx.x] = sg;
    smf[threadIdx.x] = sf;
    __syncthreads();
    for (int s = 128; s > 0; s >>= 1) {
        if (threadIdx.x < s) {
            smg[threadIdx.x] += smg[threadIdx.x + s];
            smf[threadIdx.x] += smf[threadIdx.x + s];
        }
        __syncthreads();
    }
    if (threadIdx.x == 0) {
        atomicAdd(&out[0], smg[0]);
        atomicAdd(&out[1], smf[0]);
    }
}

// ---------------- traces ----------------
__global__ void trace_kernel(const double* __restrict__ norms,
                             float* __restrict__ rel, float* __restrict__ absd)
{
    int k = threadIdx.x;
    if (k < NITER) {
        double a = sqrt(norms[2 * k]);
        double fn = sqrt(norms[2 * k + 1]);
        absd[k] = (float)a;
        rel[k] = (float)(a / (1e-5 + fn));
    }
}

// ---------------- host launcher ----------------
extern "C" void kernel_launch(void* const* d_in, const int* in_sizes, int n_in,
                              void* d_out, int out_size)
{
    const float* x0   = (const float*)d_in[0];
    const float* W    = (const float*)d_in[1];
    const float* bias = (const float*)d_in[2];

    float* out = (float*)d_out;
    float* res  = out;                                   // [2048, 2048]
    float* X    = out + (size_t)BSZ * D;                 // [2048, 6, 2048]
    float* rel  = out + (size_t)BSZ * D + (size_t)BSZ * MM * D;  // [1, 29]
    float* absd = rel + NITER;                           // [1, 29]

    float* Fp; float* alphap; float* GGtp; double* normsp;
    cudaGetSymbolAddress((void**)&Fp, g_F);
    cudaGetSymbolAddress((void**)&alphap, g_alpha);
    cudaGetSymbolAddress((void**)&GGtp, g_GGt);
    cudaGetSymbolAddress((void**)&normsp, g_norms);

    zero_norms_kernel<<<1, 64>>>(normsp);

    // X[:,0] = x0 ; F[:,0] = tanh(x0 @ W + b)
    scatter_x0_kernel<<<(BSZ * D + 255) / 256, 256>>>(x0, X);
    {
        dim3 grid(D / 128, BSZ / 128);
        gemm_bias_tanh_kernel<<<grid, 256>>>(x0, D, W, bias, Fp, LDF);
    }

    for (int k = 1; k < THRESH; k++) {
        int n = (k < MM) ? k : MM;
        int up = k % MM;

        gram_kernel<<<BSZ, 256>>>(Fp, X, GGtp, n);
        solve_kernel<<<BSZ / 256, 256>>>(GGtp, alphap, n);
        {
            dim3 grid(D / 256, BSZ);
            combine_kernel<<<grid, 256>>>(Fp, alphap, X, n, up);
        }
        {
            dim3 grid(D / 128, BSZ / 128);
            gemm_bias_tanh_kernel<<<grid, 256>>>(X + up * D, LDF, W, bias,
                                                 Fp + up * D, LDF);
        }
        norm_kernel<<<512, 256>>>(Fp, X, up, normsp + 2 * (k - 1));
    }

    gather_result_kernel<<<(BSZ * D + 255) / 256, 256>>>(X, res, (THRESH - 1) % MM);
    trace_kernel<<<1, 32>>>(normsp, rel, absd);
}

// round 4
// speedup vs baseline: 2.2434x; 2.2434x over previous
#include <cuda_runtime.h>
#include <cuda.h>
#include <cuda_bf16.h>
#include <cstdint>

// Problem constants
#define BSZ   2048
#define D     2048
#define MM    6
#define THRESH 30
#define LAM   1.0e-4f
#define LDF   (MM*D)          // 12288
#define NITER (THRESH-1)      // 29

// GEMM tiling
#define TMt   128             // M tile per CTA
#define TNt   256             // N tile per CTA
#define TKt   64              // K chunk (64 bf16 = 128B rows, SW128)
#define KITERS (D / TKt)      // 32
#define A_BYTES (TMt * TKt * 2)           // 16384
#define W_BYTES (TNt * TKt * 2)           // 32768
#define STAGE_BYTES (2*A_BYTES + 2*W_BYTES)  // 98304
#define SMEM_TOTAL (2*STAGE_BYTES + 2048)    // ctrl + 1024-align slack

// ---------------- device scratch ----------------
__device__ float         g_F[(size_t)BSZ * MM * D];
__device__ __nv_bfloat16 g_Ahi[(size_t)BSZ * D];
__device__ __nv_bfloat16 g_Alo[(size_t)BSZ * D];
__device__ __nv_bfloat16 g_Whi[(size_t)D * D];   // [N,K] transposed
__device__ __nv_bfloat16 g_Wlo[(size_t)D * D];
__device__ float         g_alpha[BSZ * 8];
__device__ float         g_GGt[BSZ * 36];
__device__ double        g_norms[2 * NITER + 2];

// ---------------- PTX helpers ----------------
__device__ __forceinline__ uint32_t smem_u32(const void* p) {
    uint32_t a;
    asm("{ .reg .u64 t; cvta.to.shared.u64 t, %1; cvt.u32.u64 %0, t; }" : "=r"(a) : "l"(p));
    return a;
}
#define MBAR_INIT(a, c) asm volatile("mbarrier.init.shared.b64 [%0], %1;" :: "r"(a), "r"(c) : "memory")
#define MBAR_EXPECT_TX(a, b) asm volatile("mbarrier.arrive.expect_tx.shared.b64 _, [%0], %1;" :: "r"(a), "r"(b) : "memory")
#define MBAR_WAIT(a, ph) do { \
    uint32_t _m = (a); uint32_t _p = (ph); \
    asm volatile("{\n\t.reg .pred P1;\n\tWL_%=:\n\t" \
        "mbarrier.try_wait.parity.acquire.cta.shared::cta.b64 P1, [%0], %1, 0x989680;\n\t" \
        "@P1 bra.uni WD_%=;\n\tbra.uni WL_%=;\n\tWD_%=:\n\t}" \
        :: "r"(_m), "r"(_p) : "memory"); \
} while (0)

__device__ __forceinline__ void tma2d(uint32_t dst, const CUtensorMap* tm, int x, int y, uint32_t bar) {
    asm volatile(
        "cp.async.bulk.tensor.2d.shared::cta.global.tile.mbarrier::complete_tx::bytes "
        "[%0], [%1, {%2, %3}], [%4];"
        :: "r"(dst), "l"(tm), "r"(x), "r"(y), "r"(bar) : "memory");
}

#define LDSM4(r, addr) \
    asm volatile("ldmatrix.sync.aligned.m8n8.x4.shared.b16 {%0,%1,%2,%3}, [%4];" \
        : "=r"((r)[0]), "=r"((r)[1]), "=r"((r)[2]), "=r"((r)[3]) : "r"(addr))

#define MMA16816(d, a, b0, b1) \
    asm volatile("mma.sync.aligned.m16n8k16.row.col.f32.bf16.bf16.f32 " \
        "{%0,%1,%2,%3}, {%4,%5,%6,%7}, {%8,%9}, {%0,%1,%2,%3};" \
        : "+f"((d)[0]), "+f"((d)[1]), "+f"((d)[2]), "+f"((d)[3]) \
        : "r"((a)[0]), "r"((a)[1]), "r"((a)[2]), "r"((a)[3]), "r"(b0), "r"(b1))

__device__ __forceinline__ void split32(float v, __nv_bfloat16& hi, __nv_bfloat16& lo) {
    hi = __float2bfloat16(v);
    lo = __float2bfloat16(v - __bfloat162float(hi));
}

__device__ __forceinline__ float fast_tanh(float x) {
    float ax = fabsf(x);
    float e = __expf(2.0f * ax);
    float r = 1.0f - __fdividef(2.0f, e + 1.0f);
    return copysignf(r, x);
}

// ---------------- HMMA GEMM: C = tanh(A @ W^T + bias) ----------------
__global__ __launch_bounds__(512, 1)
void mma_gemm_kernel(const __grid_constant__ CUtensorMap tmAhi,
                     const __grid_constant__ CUtensorMap tmAlo,
                     const __grid_constant__ CUtensorMap tmWhi,
                     const __grid_constant__ CUtensorMap tmWlo,
                     const float* __restrict__ bias,
                     float* __restrict__ C, int ldc)
{
    extern __shared__ char smem[];
    const uint32_t sb = smem_u32(smem);
    // SW128 swizzle derives from absolute SMEM addr bits [7:9] -> tile base MUST be 1024-aligned.
    const uint32_t stage0 = (sb + 1024 + 1023) & ~1023u;
    const int tid = threadIdx.x;
    const int lane = tid & 31;
    const int w = tid >> 5;
    const int wm = w & 3;        // 4 warps over M (32 rows each)
    const int wn = w >> 2;       // 4 warps over N (64 cols each)
    const int bm = blockIdx.y * TMt;
    const int bn = blockIdx.x * TNt;

    const uint32_t FULL[2] = { sb, sb + 8 };

    if (tid == 0) {
        MBAR_INIT(FULL[0], 1);
        MBAR_INIT(FULL[1], 1);
    }
    __syncthreads();

    if (tid == 0) {
        #pragma unroll
        for (int s = 0; s < 2; s++) {
            uint32_t st = stage0 + s * STAGE_BYTES;
            MBAR_EXPECT_TX(FULL[s], STAGE_BYTES);
            tma2d(st,                         &tmAhi, s * TKt, bm, FULL[s]);
            tma2d(st + A_BYTES,               &tmAlo, s * TKt, bm, FULL[s]);
            tma2d(st + 2 * A_BYTES,           &tmWhi, s * TKt, bn, FULL[s]);
            tma2d(st + 2 * A_BYTES + W_BYTES, &tmWlo, s * TKt, bn, FULL[s]);
        }
    }

    float acc[2][8][4];
    #pragma unroll
    for (int mt = 0; mt < 2; mt++)
        #pragma unroll
        for (int nt = 0; nt < 8; nt++)
            #pragma unroll
            for (int q = 0; q < 4; q++) acc[mt][nt][q] = 0.f;

    // lane-constant address pieces (SW128: 16B chunk c -> c ^ (row&7))
    const uint32_t xorv = (uint32_t)(lane & 7) << 4;
    const uint32_t a_r = lane & 15;
    const uint32_t a_b = (uint32_t)(lane >> 4) << 4;
    const uint32_t b_r = ((uint32_t)(lane >> 4) << 3) + (lane & 7);
    const uint32_t b_b = (uint32_t)((lane >> 3) & 1) << 4;

    for (int i = 0; i < KITERS; i++) {
        const int buf = i & 1;
        const int ph = (i >> 1) & 1;
        MBAR_WAIT(FULL[buf], ph);

        const uint32_t st = stage0 + buf * STAGE_BYTES;
        const uint32_t Ahi_b = st;
        const uint32_t Alo_b = st + A_BYTES;
        const uint32_t Whi_b = st + 2 * A_BYTES;
        const uint32_t Wlo_b = st + 2 * A_BYTES + W_BYTES;

        #pragma unroll
        for (int k16 = 0; k16 < 4; k16++) {
            uint32_t ahi[2][4], alo[2][4];
            #pragma unroll
            for (int mt = 0; mt < 2; mt++) {
                uint32_t R = wm * 32 + mt * 16 + a_r;
                uint32_t B = a_b + k16 * 32;
                uint32_t off = R * 128 + (B ^ xorv);
                LDSM4(ahi[mt], Ahi_b + off);
                LDSM4(alo[mt], Alo_b + off);
            }
            #pragma unroll
            for (int p = 0; p < 4; p++) {
                uint32_t R = wn * 64 + p * 16 + b_r;
                uint32_t B = b_b + k16 * 32;
                uint32_t off = R * 128 + (B ^ xorv);
                uint32_t wh[4], wl[4];
                LDSM4(wh, Whi_b + off);
                LDSM4(wl, Wlo_b + off);
                #pragma unroll
                for (int mt = 0; mt < 2; mt++) {
                    #pragma unroll
                    for (int q = 0; q < 2; q++) {
                        float* d = acc[mt][2 * p + q];
                        MMA16816(d, ahi[mt], wh[2 * q], wh[2 * q + 1]);
                        MMA16816(d, ahi[mt], wl[2 * q], wl[2 * q + 1]);
                        MMA16816(d, alo[mt], wh[2 * q], wh[2 * q + 1]);
                    }
                }
            }
        }
        __syncthreads();
        if (tid == 0 && i + 2 < KITERS) {
            MBAR_EXPECT_TX(FULL[buf], STAGE_BYTES);
            int k0 = (i + 2) * TKt;
            tma2d(st,                         &tmAhi, k0, bm, FULL[buf]);
            tma2d(st + A_BYTES,               &tmAlo, k0, bm, FULL[buf]);
            tma2d(st + 2 * A_BYTES,           &tmWhi, k0, bn, FULL[buf]);
            tma2d(st + 2 * A_BYTES + W_BYTES, &tmWlo, k0, bn, FULL[buf]);
        }
    }

    // epilogue: bias + tanh, write fp32
    const int r_in = lane >> 2;
    const int c_in = (lane & 3) * 2;
    #pragma unroll
    for (int mt = 0; mt < 2; mt++) {
        const int row = bm + wm * 32 + mt * 16 + r_in;
        #pragma unroll
        for (int nt = 0; nt < 8; nt++) {
            const int col = bn + wn * 64 + nt * 8 + c_in;
            float2 bb = *(const float2*)(bias + col);
            float v0 = fast_tanh(acc[mt][nt][0] + bb.x);
            float v1 = fast_tanh(acc[mt][nt][1] + bb.y);
            float v2 = fast_tanh(acc[mt][nt][2] + bb.x);
            float v3 = fast_tanh(acc[mt][nt][3] + bb.y);
            *(float2*)(C + (size_t)row * ldc + col) = make_float2(v0, v1);
            *(float2*)(C + (size_t)(row + 8) * ldc + col) = make_float2(v2, v3);
        }
    }
}

// ---------------- W transpose + bf16 split (once per launch) ----------------
__global__ __launch_bounds__(1024)
void wsplit_kernel(const float* __restrict__ W,
                   __nv_bfloat16* __restrict__ Whi, __nv_bfloat16* __restrict__ Wlo)
{
    __shared__ float t[32][33];
    int n0 = blockIdx.x * 32, k0 = blockIdx.y * 32;
    t[threadIdx.y][threadIdx.x] = W[(size_t)(k0 + threadIdx.y) * D + n0 + threadIdx.x];
    __syncthreads();
    float v = t[threadIdx.x][threadIdx.y];
    __nv_bfloat16 hi, lo; split32(v, hi, lo);
    size_t o = (size_t)(n0 + threadIdx.y) * D + k0 + threadIdx.x;
    Whi[o] = hi; Wlo[o] = lo;
}

// ---------------- small utility kernels ----------------
__global__ void zero_norms_kernel(double* norms) {
    int i = threadIdx.x;
    if (i < 2 * NITER + 2) norms[i] = 0.0;
}

__global__ void scatter_x0_kernel(const float* __restrict__ x0, float* __restrict__ X,
                                  __nv_bfloat16* __restrict__ Ahi, __nv_bfloat16* __restrict__ Alo) {
    int idx = blockIdx.x * blockDim.x + threadIdx.x;
    if (idx >= BSZ * D) return;
    int b = idx >> 11;
    int c = idx & (D - 1);
    float v = x0[idx];
    X[(size_t)b * LDF + c] = v;
    __nv_bfloat16 hi, lo; split32(v, hi, lo);
    Ahi[idx] = hi; Alo[idx] = lo;
}

__global__ void gather_result_kernel(const float* __restrict__ X, float* __restrict__ res, int up) {
    int idx = blockIdx.x * blockDim.x + threadIdx.x;
    if (idx >= BSZ * D) return;
    int b = idx >> 11;
    int c = idx & (D - 1);
    res[idx] = X[(size_t)b * LDF + up * D + c];
}

// ---------------- batched Gram ----------------
__global__ __launch_bounds__(256)
void gram_kernel(const float* __restrict__ F, const float* __restrict__ X,
                 float* __restrict__ GGt, int n)
{
    int b = blockIdx.x;
    const float* Fb = F + (size_t)b * LDF;
    const float* Xb = X + (size_t)b * LDF;

    float acc[21];
#pragma unroll
    for (int p = 0; p < 21; p++) acc[p] = 0.f;

    for (int dd = threadIdx.x; dd < D; dd += 256) {
        float g[6];
#pragma unroll
        for (int i = 0; i < 6; i++)
            g[i] = (i < n) ? (Fb[i * D + dd] - Xb[i * D + dd]) : 0.f;
        int p = 0;
#pragma unroll
        for (int i = 0; i < 6; i++)
#pragma unroll
            for (int j = i; j < 6; j++) { acc[p] += g[i] * g[j]; p++; }
    }

    __shared__ float sm[256][21];
#pragma unroll
    for (int p = 0; p < 21; p++) sm[threadIdx.x][p] = acc[p];
    __syncthreads();
    for (int s = 128; s > 0; s >>= 1) {
        if (threadIdx.x < s) {
#pragma unroll
            for (int p = 0; p < 21; p++) sm[threadIdx.x][p] += sm[threadIdx.x + s][p];
        }
        __syncthreads();
    }
    if (threadIdx.x == 0) {
        float* out = GGt + (size_t)b * 36;
        int p = 0;
        for (int i = 0; i < 6; i++)
            for (int j = i; j < 6; j++) {
                float v = sm[0][p++];
                if (i == j) v += LAM;
                out[i * 6 + j] = v;
                out[j * 6 + i] = v;
            }
    }
}

// ---------------- bordered solve ----------------
__global__ void solve_kernel(const float* __restrict__ GGt, float* __restrict__ alpha, int n)
{
    int b = blockIdx.x * blockDim.x + threadIdx.x;
    if (b >= BSZ) return;
    const int s = n + 1;
    float H[7][7];
    float y[7];
    H[0][0] = 0.f; y[0] = 1.f;
    for (int i = 1; i < s; i++) { H[0][i] = 1.f; H[i][0] = 1.f; y[i] = 0.f; }
    const float* G = GGt + (size_t)b * 36;
    for (int i = 0; i < n; i++)
        for (int j = 0; j < n; j++)
            H[i + 1][j + 1] = G[i * 6 + j];

    for (int c = 0; c < s; c++) {
        int piv = c;
        float mx = fabsf(H[c][c]);
        for (int r = c + 1; r < s; r++) {
            float v = fabsf(H[r][c]);
            if (v > mx) { mx = v; piv = r; }
        }
        if (piv != c) {
            for (int cc = 0; cc < s; cc++) { float t = H[c][cc]; H[c][cc] = H[piv][cc]; H[piv][cc] = t; }
            float t = y[c]; y[c] = y[piv]; y[piv] = t;
        }
        float inv = 1.f / H[c][c];
        for (int r = c + 1; r < s; r++) {
            float f = H[r][c] * inv;
            if (f != 0.f) {
                for (int cc = c; cc < s; cc++) H[r][cc] -= f * H[c][cc];
                y[r] -= f * y[c];
            }
        }
    }
    float sol[7];
    for (int r = s - 1; r >= 0; r--) {
        float a = y[r];
        for (int cc = r + 1; cc < s; cc++) a -= H[r][cc] * sol[cc];
        sol[r] = a / H[r][r];
    }
    float* ab = alpha + b * 8;
    for (int i = 0; i < 6; i++) ab[i] = (i < n) ? sol[i + 1] : 0.f;
}

// ---------------- combine + bf16 split of xnew ----------------
__global__ __launch_bounds__(256)
void combine_kernel(const float* __restrict__ F, const float* __restrict__ alpha,
                    float* __restrict__ X,
                    __nv_bfloat16* __restrict__ Ahi, __nv_bfloat16* __restrict__ Alo,
                    int n, int up)
{
    int b = blockIdx.y;
    int col = blockIdx.x * 256 + threadIdx.x;
    const float* Fb = F + (size_t)b * LDF;
    const float* ab = alpha + b * 8;
    float acc = 0.f;
#pragma unroll
    for (int i = 0; i < 6; i++)
        if (i < n) acc += ab[i] * Fb[i * D + col];
    X[(size_t)b * LDF + up * D + col] = acc;
    __nv_bfloat16 hi, lo; split32(acc, hi, lo);
    int idx = b * D + col;
    Ahi[idx] = hi; Alo[idx] = lo;
}

// ---------------- norms ----------------
__global__ __launch_bounds__(256)
void norm_kernel(const float* __restrict__ F, const float* __restrict__ X,
                 int up, double* __restrict__ out)
{
    double sg = 0.0, sf = 0.0;
    int total = BSZ * D;
    for (int idx = blockIdx.x * blockDim.x + threadIdx.x; idx < total;
         idx += gridDim.x * blockDim.x) {
        int b = idx >> 11;
        int c = idx & (D - 1);
        size_t off = (size_t)b * LDF + up * D + c;
        float f = F[off];
        float x = X[off];
        float g = f - x;
        sg += (double)g * (double)g;
        sf += (double)f * (double)f;
    }
    __shared__ double smg[256];
    __shared__ double smf[256];
    smg[threadIdx.x] = sg; smf[threadIdx.x] = sf;
    __syncthreads();
    for (int s = 128; s > 0; s >>= 1) {
        if (threadIdx.x < s) {
            smg[threadIdx.x] += smg[threadIdx.x + s];
            smf[threadIdx.x] += smf[threadIdx.x + s];
        }
        __syncthreads();
    }
    if (threadIdx.x == 0) { atomicAdd(&out[0], smg[0]); atomicAdd(&out[1], smf[0]); }
}

__global__ void trace_kernel(const double* __restrict__ norms,
                             float* __restrict__ rel, float* __restrict__ absd)
{
    int k = threadIdx.x;
    if (k < NITER) {
        double a = sqrt(norms[2 * k]);
        double fn = sqrt(norms[2 * k + 1]);
        absd[k] = (float)a;
        rel[k] = (float)(a / (1e-5 + fn));
    }
}

// ---------------- host ----------------
typedef CUresult (*PFN_tmEncode)(CUtensorMap*, CUtensorMapDataType, cuuint32_t, void*,
                                 const cuuint64_t*, const cuuint64_t*, const cuuint32_t*,
                                 const cuuint32_t*, CUtensorMapInterleave, CUtensorMapSwizzle,
                                 CUtensorMapL2promotion, CUtensorMapFloatOOBfill);

static void make_tm(PFN_tmEncode enc, CUtensorMap* tm, void* ptr, uint32_t box1) {
    cuuint64_t dims[2] = { (cuuint64_t)D, (cuuint64_t)D };
    cuuint64_t strides[1] = { (cuuint64_t)D * sizeof(__nv_bfloat16) };
    cuuint32_t box[2] = { TKt, box1 };
    cuuint32_t es[2] = { 1, 1 };
    enc(tm, CU_TENSOR_MAP_DATA_TYPE_BFLOAT16, 2, ptr, dims, strides, box, es,
        CU_TENSOR_MAP_INTERLEAVE_NONE, CU_TENSOR_MAP_SWIZZLE_128B,
        CU_TENSOR_MAP_L2_PROMOTION_L2_128B, CU_TENSOR_MAP_FLOAT_OOB_FILL_NONE);
}

extern "C" void kernel_launch(void* const* d_in, const int* in_sizes, int n_in,
                              void* d_out, int out_size)
{
    const float* x0   = (const float*)d_in[0];
    const float* W    = (const float*)d_in[1];
    const float* bias = (const float*)d_in[2];

    float* out = (float*)d_out;
    float* res  = out;
    float* X    = out + (size_t)BSZ * D;
    float* rel  = out + (size_t)BSZ * D + (size_t)BSZ * MM * D;
    float* absd = rel + NITER;

    float* Fp; __nv_bfloat16 *Ahip, *Alop, *Whip, *Wlop;
    float *alphap, *GGtp; double* normsp;
    cudaGetSymbolAddress((void**)&Fp, g_F);
    cudaGetSymbolAddress((void**)&Ahip, g_Ahi);
    cudaGetSymbolAddress((void**)&Alop, g_Alo);
    cudaGetSymbolAddress((void**)&Whip, g_Whi);
    cudaGetSymbolAddress((void**)&Wlop, g_Wlo);
    cudaGetSymbolAddress((void**)&alphap, g_alpha);
    cudaGetSymbolAddress((void**)&GGtp, g_GGt);
    cudaGetSymbolAddress((void**)&normsp, g_norms);

    PFN_tmEncode enc = nullptr;
    {
        void* fp = nullptr;
        cudaDriverEntryPointQueryResult qr;
        cudaGetDriverEntryPoint("cuTensorMapEncodeTiled", &fp, cudaEnableDefault, &qr);
        enc = (PFN_tmEncode)fp;
    }
    CUtensorMap tmAhi, tmAlo, tmWhi, tmWlo;
    make_tm(enc, &tmAhi, Ahip, TMt);
    make_tm(enc, &tmAlo, Alop, TMt);
    make_tm(enc, &tmWhi, Whip, TNt);
    make_tm(enc, &tmWlo, Wlop, TNt);

    cudaFuncSetAttribute(mma_gemm_kernel, cudaFuncAttributeMaxDynamicSharedMemorySize, SMEM_TOTAL);

    zero_norms_kernel<<<1, 64>>>(normsp);

    {
        dim3 blk(32, 32), grd(D / 32, D / 32);
        wsplit_kernel<<<grd, blk>>>(W, Whip, Wlop);
    }

    scatter_x0_kernel<<<(BSZ * D + 255) / 256, 256>>>(x0, X, Ahip, Alop);
    {
        dim3 grid(D / TNt, BSZ / TMt);
        mma_gemm_kernel<<<grid, 512, SMEM_TOTAL>>>(tmAhi, tmAlo, tmWhi, tmWlo, bias, Fp, LDF);
    }

    for (int k = 1; k < THRESH; k++) {
        int n = (k < MM) ? k : MM;
        int up = k % MM;

        gram_kernel<<<BSZ, 256>>>(Fp, X, GGtp, n);
        solve_kernel<<<BSZ / 256, 256>>>(GGtp, alphap, n);
        {
            dim3 grid(D / 256, BSZ);
            combine_kernel<<<grid, 256>>>(Fp, alphap, X, Ahip, Alop, n, up);
        }
        {
            dim3 grid(D / TNt, BSZ / TMt);
            mma_gemm_kernel<<<grid, 512, SMEM_TOTAL>>>(tmAhi, tmAlo, tmWhi, tmWlo, bias,
                                                       Fp + up * D, LDF);
        }
        norm_kernel<<<512, 256>>>(Fp, X, up, normsp + 2 * (k - 1));
    }

    gather_result_kernel<<<(BSZ * D + 255) / 256, 256>>>(X, res, (THRESH - 1) % MM);
    trace_kernel<<<1, 32>>>(normsp, rel, absd);
}

// round 5
// speedup vs baseline: 3.0577x; 1.3630x over previous
#include <cuda_runtime.h>
#include <cuda.h>
#include <cuda_bf16.h>
#include <cstdint>

// Problem constants
#define BSZ   2048
#define D     2048
#define MM    6
#define THRESH 30
#define LAM   1.0e-4f
#define LDF   (MM*D)          // 12288
#define NITER (THRESH-1)      // 29

// GEMM tiling
#define TMt   128
#define TNt   256
#define TKt   64              // 64 bf16 = 128B rows, SW128
#define KITERS (D / TKt)      // 32
#define A_BYTES (TMt * TKt * 2)              // 16384
#define W_BYTES (TNt * TKt * 2)              // 32768
#define STAGE_BYTES (2*A_BYTES + 2*W_BYTES)  // 98304
#define SMEM_TOTAL (2*STAGE_BYTES + 2048)

// ---------------- device scratch ----------------
__device__ float         g_F[(size_t)BSZ * MM * D];
__device__ float         g_G[(size_t)BSZ * MM * D];   // G = F - X history
__device__ __nv_bfloat16 g_Ahi[(size_t)BSZ * D];
__device__ __nv_bfloat16 g_Alo[(size_t)BSZ * D];
__device__ __nv_bfloat16 g_Whi[(size_t)D * D];        // [N,K] transposed
__device__ __nv_bfloat16 g_Wlo[(size_t)D * D];
__device__ float         g_alpha[BSZ * 8];
__device__ float         g_GGt[BSZ * 36];
__device__ double        g_norms[2 * NITER + 2];

// ---------------- PTX helpers ----------------
__device__ __forceinline__ uint32_t smem_u32(const void* p) {
    uint32_t a;
    asm("{ .reg .u64 t; cvta.to.shared.u64 t, %1; cvt.u32.u64 %0, t; }" : "=r"(a) : "l"(p));
    return a;
}
#define MBAR_INIT(a, c) asm volatile("mbarrier.init.shared.b64 [%0], %1;" :: "r"(a), "r"(c) : "memory")
#define MBAR_EXPECT_TX(a, b) asm volatile("mbarrier.arrive.expect_tx.shared.b64 _, [%0], %1;" :: "r"(a), "r"(b) : "memory")
#define MBAR_ARRIVE(a) asm volatile("mbarrier.arrive.shared.b64 _, [%0];" :: "r"(a) : "memory")
#define MBAR_WAIT(a, ph) do { \
    uint32_t _m = (a); uint32_t _p = (ph); \
    asm volatile("{\n\t.reg .pred P1;\n\tWL_%=:\n\t" \
        "mbarrier.try_wait.parity.acquire.cta.shared::cta.b64 P1, [%0], %1, 0x989680;\n\t" \
        "@P1 bra.uni WD_%=;\n\tbra.uni WL_%=;\n\tWD_%=:\n\t}" \
        :: "r"(_m), "r"(_p) : "memory"); \
} while (0)

__device__ __forceinline__ void tma2d(uint32_t dst, const CUtensorMap* tm, int x, int y, uint32_t bar) {
    asm volatile(
        "cp.async.bulk.tensor.2d.shared::cta.global.tile.mbarrier::complete_tx::bytes "
        "[%0], [%1, {%2, %3}], [%4];"
        :: "r"(dst), "l"(tm), "r"(x), "r"(y), "r"(bar) : "memory");
}

#define LDSM4(r, addr) \
    asm volatile("ldmatrix.sync.aligned.m8n8.x4.shared.b16 {%0,%1,%2,%3}, [%4];" \
        : "=r"((r)[0]), "=r"((r)[1]), "=r"((r)[2]), "=r"((r)[3]) : "r"(addr))

#define MMA16816(d, a, b0, b1) \
    asm volatile("mma.sync.aligned.m16n8k16.row.col.f32.bf16.bf16.f32 " \
        "{%0,%1,%2,%3}, {%4,%5,%6,%7}, {%8,%9}, {%0,%1,%2,%3};" \
        : "+f"((d)[0]), "+f"((d)[1]), "+f"((d)[2]), "+f"((d)[3]) \
        : "r"((a)[0]), "r"((a)[1]), "r"((a)[2]), "r"((a)[3]), "r"(b0), "r"(b1))

__device__ __forceinline__ void split32(float v, __nv_bfloat16& hi, __nv_bfloat16& lo) {
    hi = __float2bfloat16(v);
    lo = __float2bfloat16(v - __bfloat162float(hi));
}

__device__ __forceinline__ float fast_tanh(float x) {
    float ax = fabsf(x);
    float e = __expf(2.0f * ax);
    float r = 1.0f - __fdividef(2.0f, e + 1.0f);
    return copysignf(r, x);
}

// ---------------- HMMA GEMM: F = tanh(A @ W^T + bias); G = F - X; norms ----------------
__global__ __launch_bounds__(512, 1)
void mma_gemm_kernel(const __grid_constant__ CUtensorMap tmAhi,
                     const __grid_constant__ CUtensorMap tmAlo,
                     const __grid_constant__ CUtensorMap tmWhi,
                     const __grid_constant__ CUtensorMap tmWlo,
                     const float* __restrict__ bias,
                     float* __restrict__ C,
                     const float* __restrict__ Xcur,   // xnew slot (fp32)
                     float* __restrict__ Gout,         // G slot
                     double* norms_slot,               // may be null
                     int ldc)
{
    extern __shared__ char smem[];
    __shared__ float red[2][16];
    const uint32_t sb = smem_u32(smem);
    const uint32_t stage0 = (sb + 1024 + 1023) & ~1023u;   // SW128 needs 1024-aligned tiles
    const int tid = threadIdx.x;
    const int lane = tid & 31;
    const int w = tid >> 5;
    const int wm = w & 3;
    const int wn = w >> 2;
    const int bm = blockIdx.y * TMt;
    const int bn = blockIdx.x * TNt;

    const uint32_t FULL[2]  = { sb,      sb + 8  };
    const uint32_t EMPTY[2] = { sb + 16, sb + 24 };

    if (tid == 0) {
        MBAR_INIT(FULL[0], 1);  MBAR_INIT(FULL[1], 1);
        MBAR_INIT(EMPTY[0], 16); MBAR_INIT(EMPTY[1], 16);
    }
    __syncthreads();

    if (tid == 0) {
        #pragma unroll
        for (int s = 0; s < 2; s++) {
            uint32_t st = stage0 + s * STAGE_BYTES;
            MBAR_EXPECT_TX(FULL[s], STAGE_BYTES);
            tma2d(st,                         &tmAhi, s * TKt, bm, FULL[s]);
            tma2d(st + A_BYTES,               &tmAlo, s * TKt, bm, FULL[s]);
            tma2d(st + 2 * A_BYTES,           &tmWhi, s * TKt, bn, FULL[s]);
            tma2d(st + 2 * A_BYTES + W_BYTES, &tmWlo, s * TKt, bn, FULL[s]);
        }
    }

    float acc[2][8][4];
    #pragma unroll
    for (int mt = 0; mt < 2; mt++)
        #pragma unroll
        for (int nt = 0; nt < 8; nt++)
            #pragma unroll
            for (int q = 0; q < 4; q++) acc[mt][nt][q] = 0.f;

    const uint32_t xorv = (uint32_t)(lane & 7) << 4;
    const uint32_t a_r = lane & 15;
    const uint32_t a_b = (uint32_t)(lane >> 4) << 4;
    const uint32_t b_r = ((uint32_t)(lane >> 4) << 3) + (lane & 7);
    const uint32_t b_b = (uint32_t)((lane >> 3) & 1) << 4;

    for (int i = 0; i < KITERS; i++) {
        const int buf = i & 1;
        const int ph = (i >> 1) & 1;
        MBAR_WAIT(FULL[buf], ph);

        const uint32_t st = stage0 + buf * STAGE_BYTES;
        const uint32_t Ahi_b = st;
        const uint32_t Alo_b = st + A_BYTES;
        const uint32_t Whi_b = st + 2 * A_BYTES;
        const uint32_t Wlo_b = st + 2 * A_BYTES + W_BYTES;

        #pragma unroll
        for (int k16 = 0; k16 < 4; k16++) {
            uint32_t ahi[2][4], alo[2][4];
            #pragma unroll
            for (int mt = 0; mt < 2; mt++) {
                uint32_t R = wm * 32 + mt * 16 + a_r;
                uint32_t B = a_b + k16 * 32;
                uint32_t off = R * 128 + (B ^ xorv);
                LDSM4(ahi[mt], Ahi_b + off);
                LDSM4(alo[mt], Alo_b + off);
            }
            #pragma unroll
            for (int p = 0; p < 4; p++) {
                uint32_t R = wn * 64 + p * 16 + b_r;
                uint32_t B = b_b + k16 * 32;
                uint32_t off = R * 128 + (B ^ xorv);
                uint32_t wh[4], wl[4];
                LDSM4(wh, Whi_b + off);
                LDSM4(wl, Wlo_b + off);
                #pragma unroll
                for (int mt = 0; mt < 2; mt++) {
                    #pragma unroll
                    for (int q = 0; q < 2; q++) {
                        float* d = acc[mt][2 * p + q];
                        MMA16816(d, ahi[mt], wh[2 * q], wh[2 * q + 1]);
                        MMA16816(d, ahi[mt], wl[2 * q], wl[2 * q + 1]);
                        MMA16816(d, alo[mt], wh[2 * q], wh[2 * q + 1]);
                    }
                }
            }
        }
        // this warp is done reading buf's smem (release via arrive)
        if (lane == 0) MBAR_ARRIVE(EMPTY[buf]);
        if (tid == 0 && i + 2 < KITERS) {
            MBAR_WAIT(EMPTY[buf], ph);   // all 16 warps done with buf
            MBAR_EXPECT_TX(FULL[buf], STAGE_BYTES);
            int k0 = (i + 2) * TKt;
            tma2d(st,                         &tmAhi, k0, bm, FULL[buf]);
            tma2d(st + A_BYTES,               &tmAlo, k0, bm, FULL[buf]);
            tma2d(st + 2 * A_BYTES,           &tmWhi, k0, bn, FULL[buf]);
            tma2d(st + 2 * A_BYTES + W_BYTES, &tmWlo, k0, bn, FULL[buf]);
        }
    }

    // epilogue: bias + tanh -> F; g = f - x -> G; accumulate norms
    const int r_in = lane >> 2;
    const int c_in = (lane & 3) * 2;
    float sg = 0.f, sf = 0.f;
    #pragma unroll
    for (int mt = 0; mt < 2; mt++) {
        const int row = bm + wm * 32 + mt * 16 + r_in;
        #pragma unroll
        for (int nt = 0; nt < 8; nt++) {
            const int col = bn + wn * 64 + nt * 8 + c_in;
            float2 bb = *(const float2*)(bias + col);
            float v0 = fast_tanh(acc[mt][nt][0] + bb.x);
            float v1 = fast_tanh(acc[mt][nt][1] + bb.y);
            float v2 = fast_tanh(acc[mt][nt][2] + bb.x);
            float v3 = fast_tanh(acc[mt][nt][3] + bb.y);
            size_t o0 = (size_t)row * ldc + col;
            size_t o1 = (size_t)(row + 8) * ldc + col;
            float2 x0 = *(const float2*)(Xcur + o0);
            float2 x1 = *(const float2*)(Xcur + o1);
            float g0 = v0 - x0.x, g1 = v1 - x0.y;
            float g2 = v2 - x1.x, g3 = v3 - x1.y;
            *(float2*)(C + o0) = make_float2(v0, v1);
            *(float2*)(C + o1) = make_float2(v2, v3);
            *(float2*)(Gout + o0) = make_float2(g0, g1);
            *(float2*)(Gout + o1) = make_float2(g2, g3);
            sg += g0 * g0 + g1 * g1 + g2 * g2 + g3 * g3;
            sf += v0 * v0 + v1 * v1 + v2 * v2 + v3 * v3;
        }
    }
    if (norms_slot != nullptr) {
        #pragma unroll
        for (int s = 16; s > 0; s >>= 1) {
            sg += __shfl_xor_sync(0xFFFFFFFF, sg, s);
            sf += __shfl_xor_sync(0xFFFFFFFF, sf, s);
        }
        if (lane == 0) { red[0][w] = sg; red[1][w] = sf; }
        __syncthreads();
        if (w == 0 && lane < 16) {
            float a = red[0][lane], b = red[1][lane];
            #pragma unroll
            for (int s = 8; s > 0; s >>= 1) {
                a += __shfl_xor_sync(0xFFFF, a, s);
                b += __shfl_xor_sync(0xFFFF, b, s);
            }
            if (lane == 0) {
                atomicAdd(&norms_slot[0], (double)a);
                atomicAdd(&norms_slot[1], (double)b);
            }
        }
    }
}

// ---------------- W transpose + bf16 split ----------------
__global__ __launch_bounds__(1024)
void wsplit_kernel(const float* __restrict__ W,
                   __nv_bfloat16* __restrict__ Whi, __nv_bfloat16* __restrict__ Wlo)
{
    __shared__ float t[32][33];
    int n0 = blockIdx.x * 32, k0 = blockIdx.y * 32;
    t[threadIdx.y][threadIdx.x] = W[(size_t)(k0 + threadIdx.y) * D + n0 + threadIdx.x];
    __syncthreads();
    float v = t[threadIdx.x][threadIdx.y];
    __nv_bfloat16 hi, lo; split32(v, hi, lo);
    size_t o = (size_t)(n0 + threadIdx.y) * D + k0 + threadIdx.x;
    Whi[o] = hi; Wlo[o] = lo;
}

// ---------------- small utility kernels ----------------
__global__ void zero_norms_kernel(double* norms) {
    int i = threadIdx.x;
    if (i < 2 * NITER + 2) norms[i] = 0.0;
}

__global__ void scatter_x0_kernel(const float* __restrict__ x0, float* __restrict__ X,
                                  __nv_bfloat16* __restrict__ Ahi, __nv_bfloat16* __restrict__ Alo) {
    int idx = blockIdx.x * blockDim.x + threadIdx.x;
    if (idx >= BSZ * D) return;
    int b = idx >> 11;
    int c = idx & (D - 1);
    float v = x0[idx];
    X[(size_t)b * LDF + c] = v;
    __nv_bfloat16 hi, lo; split32(v, hi, lo);
    Ahi[idx] = hi; Alo[idx] = lo;
}

__global__ void gather_result_kernel(const float* __restrict__ X, float* __restrict__ res, int up) {
    int idx = blockIdx.x * blockDim.x + threadIdx.x;
    if (idx >= BSZ * D) return;
    int b = idx >> 11;
    int c = idx & (D - 1);
    res[idx] = X[(size_t)b * LDF + up * D + c];
}

// ---------------- batched Gram from G (float4) ----------------
__global__ __launch_bounds__(256)
void gram_kernel(const float* __restrict__ G, float* __restrict__ GGt, int n)
{
    int b = blockIdx.x;
    const float4* Gb = (const float4*)(G + (size_t)b * LDF);

    float acc[21];
#pragma unroll
    for (int p = 0; p < 21; p++) acc[p] = 0.f;

#pragma unroll
    for (int rep = 0; rep < 2; rep++) {
        int c4 = threadIdx.x + rep * 256;   // 0..511
        float4 g4[6];
#pragma unroll
        for (int j = 0; j < 6; j++) {
            if (j < n) g4[j] = Gb[j * 512 + c4];
            else g4[j] = make_float4(0.f, 0.f, 0.f, 0.f);
        }
        int p = 0;
#pragma unroll
        for (int i = 0; i < 6; i++)
#pragma unroll
            for (int j = i; j < 6; j++) {
                acc[p] += g4[i].x * g4[j].x + g4[i].y * g4[j].y
                        + g4[i].z * g4[j].z + g4[i].w * g4[j].w;
                p++;
            }
    }

    __shared__ float sm[256][21];
#pragma unroll
    for (int p = 0; p < 21; p++) sm[threadIdx.x][p] = acc[p];
    __syncthreads();
    for (int s = 128; s > 0; s >>= 1) {
        if (threadIdx.x < s) {
#pragma unroll
            for (int p = 0; p < 21; p++) sm[threadIdx.x][p] += sm[threadIdx.x + s][p];
        }
        __syncthreads();
    }
    if (threadIdx.x == 0) {
        float* out = GGt + (size_t)b * 36;
        int p = 0;
        for (int i = 0; i < 6; i++)
            for (int j = i; j < 6; j++) {
                float v = sm[0][p++];
                if (i == j) v += LAM;
                out[i * 6 + j] = v;
                out[j * 6 + i] = v;
            }
    }
}

// ---------------- bordered solve ----------------
__global__ void solve_kernel(const float* __restrict__ GGt, float* __restrict__ alpha, int n)
{
    int b = blockIdx.x * blockDim.x + threadIdx.x;
    if (b >= BSZ) return;
    const int s = n + 1;
    float H[7][7];
    float y[7];
    H[0][0] = 0.f; y[0] = 1.f;
    for (int i = 1; i < s; i++) { H[0][i] = 1.f; H[i][0] = 1.f; y[i] = 0.f; }
    const float* G = GGt + (size_t)b * 36;
    for (int i = 0; i < n; i++)
        for (int j = 0; j < n; j++)
            H[i + 1][j + 1] = G[i * 6 + j];

    for (int c = 0; c < s; c++) {
        int piv = c;
        float mx = fabsf(H[c][c]);
        for (int r = c + 1; r < s; r++) {
            float v = fabsf(H[r][c]);
            if (v > mx) { mx = v; piv = r; }
        }
        if (piv != c) {
            for (int cc = 0; cc < s; cc++) { float t = H[c][cc]; H[c][cc] = H[piv][cc]; H[piv][cc] = t; }
            float t = y[c]; y[c] = y[piv]; y[piv] = t;
        }
        float inv = 1.f / H[c][c];
        for (int r = c + 1; r < s; r++) {
            float f = H[r][c] * inv;
            if (f != 0.f) {
                for (int cc = c; cc < s; cc++) H[r][cc] -= f * H[c][cc];
                y[r] -= f * y[c];
            }
        }
    }
    float sol[7];
    for (int r = s - 1; r >= 0; r--) {
        float a = y[r];
        for (int cc = r + 1; cc < s; cc++) a -= H[r][cc] * sol[cc];
        sol[r] = a / H[r][r];
    }
    float* ab = alpha + b * 8;
    for (int i = 0; i < 6; i++) ab[i] = (i < n) ? sol[i + 1] : 0.f;
}

// ---------------- combine (float4) + bf16 split of xnew ----------------
__global__ __launch_bounds__(256)
void combine_kernel(const float* __restrict__ F, const float* __restrict__ alpha,
                    float* __restrict__ X,
                    __nv_bfloat16* __restrict__ Ahi, __nv_bfloat16* __restrict__ Alo,
                    int n, int up)
{
    int b = blockIdx.y;
    int c4 = blockIdx.x * 256 + threadIdx.x;   // 0..511
    const float4* Fb = (const float4*)(F + (size_t)b * LDF);
    const float* ab = alpha + b * 8;
    float4 acc = make_float4(0.f, 0.f, 0.f, 0.f);
#pragma unroll
    for (int j = 0; j < 6; j++) {
        if (j < n) {
            float a = ab[j];
            float4 f = Fb[j * 512 + c4];
            acc.x += a * f.x; acc.y += a * f.y; acc.z += a * f.z; acc.w += a * f.w;
        }
    }
    ((float4*)(X + (size_t)b * LDF + up * D))[c4] = acc;

    __nv_bfloat16 h0, l0, h1, l1, h2, l2, h3, l3;
    split32(acc.x, h0, l0); split32(acc.y, h1, l1);
    split32(acc.z, h2, l2); split32(acc.w, h3, l3);
    __nv_bfloat162* Ah = (__nv_bfloat162*)(Ahi + (size_t)b * D);
    __nv_bfloat162* Al = (__nv_bfloat162*)(Alo + (size_t)b * D);
    Ah[c4 * 2]     = __nv_bfloat162(h0, h1);
    Ah[c4 * 2 + 1] = __nv_bfloat162(h2, h3);
    Al[c4 * 2]     = __nv_bfloat162(l0, l1);
    Al[c4 * 2 + 1] = __nv_bfloat162(l2, l3);
}

__global__ void trace_kernel(const double* __restrict__ norms,
                             float* __restrict__ rel, float* __restrict__ absd)
{
    int k = threadIdx.x;
    if (k < NITER) {
        double a = sqrt(norms[2 * k]);
        double fn = sqrt(norms[2 * k + 1]);
        absd[k] = (float)a;
        rel[k] = (float)(a / (1e-5 + fn));
    }
}

// ---------------- host ----------------
typedef CUresult (*PFN_tmEncode)(CUtensorMap*, CUtensorMapDataType, cuuint32_t, void*,
                                 const cuuint64_t*, const cuuint64_t*, const cuuint32_t*,
                                 const cuuint32_t*, CUtensorMapInterleave, CUtensorMapSwizzle,
                                 CUtensorMapL2promotion, CUtensorMapFloatOOBfill);

static void make_tm(PFN_tmEncode enc, CUtensorMap* tm, void* ptr, uint32_t box1) {
    cuuint64_t dims[2] = { (cuuint64_t)D, (cuuint64_t)D };
    cuuint64_t strides[1] = { (cuuint64_t)D * sizeof(__nv_bfloat16) };
    cuuint32_t box[2] = { TKt, box1 };
    cuuint32_t es[2] = { 1, 1 };
    enc(tm, CU_TENSOR_MAP_DATA_TYPE_BFLOAT16, 2, ptr, dims, strides, box, es,
        CU_TENSOR_MAP_INTERLEAVE_NONE, CU_TENSOR_MAP_SWIZZLE_128B,
        CU_TENSOR_MAP_L2_PROMOTION_L2_128B, CU_TENSOR_MAP_FLOAT_OOB_FILL_NONE);
}

extern "C" void kernel_launch(void* const* d_in, const int* in_sizes, int n_in,
                              void* d_out, int out_size)
{
    const float* x0   = (const float*)d_in[0];
    const float* W    = (const float*)d_in[1];
    const float* bias = (const float*)d_in[2];

    float* out = (float*)d_out;
    float* res  = out;
    float* X    = out + (size_t)BSZ * D;
    float* rel  = out + (size_t)BSZ * D + (size_t)BSZ * MM * D;
    float* absd = rel + NITER;

    float *Fp, *Gp, *alphap, *GGtp; __nv_bfloat16 *Ahip, *Alop, *Whip, *Wlop;
    double* normsp;
    cudaGetSymbolAddress((void**)&Fp, g_F);
    cudaGetSymbolAddress((void**)&Gp, g_G);
    cudaGetSymbolAddress((void**)&Ahip, g_Ahi);
    cudaGetSymbolAddress((void**)&Alop, g_Alo);
    cudaGetSymbolAddress((void**)&Whip, g_Whi);
    cudaGetSymbolAddress((void**)&Wlop, g_Wlo);
    cudaGetSymbolAddress((void**)&alphap, g_alpha);
    cudaGetSymbolAddress((void**)&GGtp, g_GGt);
    cudaGetSymbolAddress((void**)&normsp, g_norms);

    PFN_tmEncode enc = nullptr;
    {
        void* fp = nullptr;
        cudaDriverEntryPointQueryResult qr;
        cudaGetDriverEntryPoint("cuTensorMapEncodeTiled", &fp, cudaEnableDefault, &qr);
        enc = (PFN_tmEncode)fp;
    }
    CUtensorMap tmAhi, tmAlo, tmWhi, tmWlo;
    make_tm(enc, &tmAhi, Ahip, TMt);
    make_tm(enc, &tmAlo, Alop, TMt);
    make_tm(enc, &tmWhi, Whip, TNt);
    make_tm(enc, &tmWlo, Wlop, TNt);

    cudaFuncSetAttribute(mma_gemm_kernel, cudaFuncAttributeMaxDynamicSharedMemorySize, SMEM_TOTAL);

    zero_norms_kernel<<<1, 64>>>(normsp);

    {
        dim3 blk(32, 32), grd(D / 32, D / 32);
        wsplit_kernel<<<grd, blk>>>(W, Whip, Wlop);
    }

    scatter_x0_kernel<<<(BSZ * D + 255) / 256, 256>>>(x0, X, Ahip, Alop);
    {
        dim3 grid(D / TNt, BSZ / TMt);
        mma_gemm_kernel<<<grid, 512, SMEM_TOTAL>>>(tmAhi, tmAlo, tmWhi, tmWlo, bias,
                                                   Fp, X, Gp, nullptr, LDF);
    }

    for (int k = 1; k < THRESH; k++) {
        int n = (k < MM) ? k : MM;
        int up = k % MM;

        gram_kernel<<<BSZ, 256>>>(Gp, GGtp, n);
        solve_kernel<<<BSZ / 256, 256>>>(GGtp, alphap, n);
        {
            dim3 grid(2, BSZ);
            combine_kernel<<<grid, 256>>>(Fp, alphap, X, Ahip, Alop, n, up);
        }
        {
            dim3 grid(D / TNt, BSZ / TMt);
            mma_gemm_kernel<<<grid, 512, SMEM_TOTAL>>>(tmAhi, tmAlo, tmWhi, tmWlo, bias,
                                                       Fp + up * D, X + up * D, Gp + up * D,
                                                       normsp + 2 * (k - 1), LDF);
        }
    }

    gather_result_kernel<<<(BSZ * D + 255) / 256, 256>>>(X, res, (THRESH - 1) % MM);
    trace_kernel<<<1, 32>>>(normsp, rel, absd);
}